// round 13
// baseline (speedup 1.0000x reference)
#include <cuda_runtime.h>
#include <cstdint>

#define NB      5
#define HWPX    65536
#define NP      (NB*HWPX)
#define NCH     256
#define BSHIFT  14                    // bucket = dsc >> 14 (18-bit buckets)
#define NBUCK   131072                // valid dsc < 0x80000000 -> bucket < 131072
#define TILESZ  4096
#define NTILE   (NBUCK/TILESZ)        // 32
#define WCAP    4096

// PDL: park until predecessor kernel completes (no-op if not launched dependent)
__device__ __forceinline__ void pdl_wait() {
    asm volatile("griddepcontrol.wait;" ::: "memory");
}

// ---- static device scratch (allocation-free; zero-initialized at load) ----
__device__ unsigned int       g_dsc[NP];           // descending-order key of best utility
__device__ unsigned char      g_g8[NP];            // argmax group 0/1/2
__device__ unsigned long long g_hist[NB*NBUCK];    // packed: cost | c1<<20 | c2<<40
__device__ unsigned int       g_winbits[NP/32];    // accepted-window bitmap (idempotent OR)
__device__ int                g_b0[NB];

__device__ __forceinline__ float load_budget(const void* ptr) {
    int iv = *(const int*)ptr;                       // int32 or float32 scalar
    if (iv > 0 && iv < 100000000) return (float)iv;
    return __int_as_float(iv);
}
__device__ __forceinline__ int cost_of(int g) { return (g == 0) ? 4 : (g == 1) ? 2 : 1; }

__device__ __forceinline__ void do_pixel(int p, float u0, float u1, float u2,
                                         unsigned* dsc_o, unsigned char* g_o) {
    int g = 0; float bu = u0;
    if (u1 > bu) { bu = u1; g = 1; }   // strict >: first max wins (jnp.argmax)
    if (u2 > bu) { bu = u2; g = 2; }
    bool valid = bu > 0.0f;
    unsigned int x = __float_as_uint(bu);
    unsigned int dsc = ~((x & 0x80000000u) ? ~x : (x | 0x80000000u)); // descending map
    if (!valid) dsc = 0xFFFFFFFFu;
    *dsc_o = dsc; *g_o = (unsigned char)g;
    if (valid) {
        unsigned long long inc = (unsigned long long)cost_of(g)
            | ((unsigned long long)(g == 1) << 20)
            | ((unsigned long long)(g == 2) << 40);
        atomicAdd(&g_hist[(size_t)(p >> 16) * NBUCK + (dsc >> BSHIFT)], inc);
    }
}

// ---- per-pixel argmax + packed histogram, 2 px / thread ----
__global__ void kArgmax(const float* __restrict__ util) {
    int q  = blockIdx.x * blockDim.x + threadIdx.x;   // NP/2 threads
    int p0 = q << 1;
    const float2* u = (const float2*)(util + 3 * (size_t)p0);   // 6 floats = 3x float2
    float2 a = u[0], b = u[1], c = u[2];
    unsigned d2[2]; unsigned char gg[2];
    do_pixel(p0 + 0, a.x, a.y, b.x, &d2[0], &gg[0]);
    do_pixel(p0 + 1, b.y, c.x, c.y, &d2[1], &gg[1]);
    *(uint2*)(g_dsc + p0) = make_uint2(d2[0], d2[1]);
    *(uchar2*)(g_g8 + p0) = make_uchar2(gg[0], gg[1]);
}

// ---- fused selection: 1 block (1024 thr) per batch ----
// tile sums + crossing b0 + window end b1 + dsc-scan gather + sort + greedy replay.
__global__ void kSelect(const void* __restrict__ budget_p) {
    __shared__ unsigned s_tile[NTILE];
    __shared__ unsigned s_wsum[32];
    __shared__ int s_ctile, s_b0, s_b1, s_n, s_i1;
    __shared__ unsigned s_cumbase, s_Sb;
    __shared__ unsigned long long sk[WCAP];     // 32KB window keys
    __shared__ unsigned short sp[WCAP];         // 8KB inclusive cost prefix (<=16384)
    __shared__ int s_tsum[32];

    int b = blockIdx.x, t = threadIdx.x;
    int wid = t >> 5, lane = t & 31;
    float budget = load_budget(budget_p) / (float)NB;
    const unsigned long long* hist = g_hist + (size_t)b * NBUCK;

    if (t == 0) { s_ctile = -1; s_cumbase = 0; s_b0 = NBUCK; s_Sb = 0;
                  s_n = 0; s_i1 = 0x7FFFFFFF; }
    pdl_wait();   // kArgmax results (g_hist/g_dsc/g_g8) must be complete

    // warp w sums tile w (4096 buckets), coalesced
    unsigned sum = 0;
    #pragma unroll 8
    for (int j = 0; j < TILESZ/32; j++)
        sum += (unsigned)(hist[wid*TILESZ + j*32 + lane] & 0xFFFFFu);
    #pragma unroll
    for (int off = 16; off > 0; off >>= 1) sum += __shfl_down_sync(0xffffffffu, sum, off);
    if (lane == 0) s_tile[wid] = sum;
    __syncthreads();

    if (t == 0) {   // tile-level crossing
        unsigned cum = 0;
        for (int q = 0; q < NTILE; q++) {
            unsigned c = s_tile[q];
            if ((float)(cum + c) > budget) { s_ctile = q; s_cumbase = cum; break; }
            cum += c;
        }
    }
    __syncthreads();
    int ctile = s_ctile;

    if (ctile >= 0) {   // in-tile scan: 4 buckets per thread over 4096 buckets
        int base = ctile*TILESZ + t*4;
        unsigned c4[4]; unsigned s = 0;
        #pragma unroll
        for (int k = 0; k < 4; k++) { c4[k] = (unsigned)(hist[base+k] & 0xFFFFFu); s += c4[k]; }
        unsigned inc = s;
        #pragma unroll
        for (int off = 1; off < 32; off <<= 1) {
            unsigned v = __shfl_up_sync(0xffffffffu, inc, off);
            if (lane >= off) inc += v;
        }
        if (lane == 31) s_wsum[wid] = inc;
        __syncthreads();
        if (wid == 0) {
            unsigned w = s_wsum[lane];
            #pragma unroll
            for (int off = 1; off < 32; off <<= 1) {
                unsigned v = __shfl_up_sync(0xffffffffu, w, off);
                if (lane >= off) w += v;
            }
            s_wsum[lane] = w;
        }
        __syncthreads();
        unsigned cum = s_cumbase + (inc - s) + ((wid > 0) ? s_wsum[wid-1] : 0u);
        #pragma unroll
        for (int k = 0; k < 4; k++) {   // unique first crossing among this thread's 4
            unsigned nxt = cum + c4[k];
            if ((float)nxt > budget && (float)cum <= budget) { s_b0 = base + k; s_Sb = cum; }
            cum = nxt;
        }
        __syncthreads();
    }

    int b0 = s_b0;
    if (t == 0) g_b0[b] = b0;
    if (b0 >= NBUCK) return;   // no crossing: phase-1 accepts everything valid

    if (wid == 0) {   // extend window bucket-by-bucket until >=8 cost-1 items beyond b0
        int c2cum = 0, pos = b0 + 1, b1 = NBUCK-1; bool done = false;
        while (!done && pos < NBUCK) {
            int idx = pos + lane;
            unsigned long long h = (idx < NBUCK) ? hist[idx] : 0ull;
            int k = (int)((h >> 40) & 0xFFFFFull);
            int inck = k;
            #pragma unroll
            for (int off = 1; off < 32; off <<= 1) {
                int v = __shfl_up_sync(0xffffffffu, inck, off);
                if (lane >= off) inck += v;
            }
            int tot = __shfl_sync(0xffffffffu, inck, 31);
            unsigned m = __ballot_sync(0xffffffffu, c2cum + inck >= 8);
            if (m) { b1 = min(pos + (__ffs(m) - 1), NBUCK-1); done = true; }
            else   { c2cum += tot; pos += 32; }
        }
        if (lane == 0) s_b1 = b1;
    }
    __syncthreads();
    unsigned b0u = (unsigned)b0, b1u = (unsigned)s_b1;

    // gather window items by scanning this batch's dsc plane (256KB, coalesced)
    const uint4* dscv = (const uint4*)(g_dsc + (size_t)b * HWPX);
    for (int i = t; i < HWPX/4; i += 1024) {
        uint4 d = dscv[i];
        unsigned da[4] = {d.x, d.y, d.z, d.w};
        #pragma unroll
        for (int k = 0; k < 4; k++) {
            unsigned bucket = da[k] >> BSHIFT;   // invalid dsc -> bucket 0x3FFFF > b1
            if (bucket >= b0u && bucket <= b1u) {
                int pix = i*4 + k;
                int g = (int)g_g8[b*HWPX + pix];
                int idx = atomicAdd(&s_n, 1);
                if (idx < WCAP)
                    sk[idx] = ((unsigned long long)da[k] << 24)
                            | ((unsigned long long)pix << 8) | (unsigned long long)g;
            }
        }
    }
    __syncthreads();
    int n = min(s_n, WCAP);

    // exact ranking sort (unique keys -> permutation)
    unsigned long long myk[4]; int myr[4]; int cnt = 0;
    for (int i = t; i < n; i += 1024) {
        unsigned long long k = sk[i];
        int r = 0;
        for (int j = 0; j < n; j++) r += (sk[j] < k);
        myk[cnt] = k; myr[cnt] = r; cnt++;
    }
    __syncthreads();
    for (int q = 0; q < cnt; q++) sk[myr[q]] = myk[q];
    __syncthreads();

    // block-wide inclusive prefix sum of costs (4 items / thread)
    int lo = t * 4, hi = min(lo + 4, n);
    int run = 0;
    for (int i = lo; i < hi; i++) { run += cost_of((int)(sk[i] & 0xFFu)); sp[i] = (unsigned short)run; }
    int tot = run, inc2 = tot;
    #pragma unroll
    for (int off = 1; off < 32; off <<= 1) {
        int v = __shfl_up_sync(0xffffffffu, inc2, off);
        if (lane >= off) inc2 += v;
    }
    if (lane == 31) s_tsum[wid] = inc2;
    __syncthreads();
    if (wid == 0) {
        int w = s_tsum[lane];
        #pragma unroll
        for (int off = 1; off < 32; off <<= 1) {
            int v = __shfl_up_sync(0xffffffffu, w, off);
            if (lane >= off) w += v;
        }
        s_tsum[lane] = w;
    }
    __syncthreads();
    int chunk_off = (inc2 - tot) + ((wid > 0) ? s_tsum[wid-1] : 0);
    for (int i = lo; i < hi; i++) sp[i] = (unsigned short)(sp[i] + chunk_off);
    __syncthreads();

    float base = (float)s_Sb;
    // first rejection index: first i with base + sp[i] > budget
    for (int i = lo; i < hi; i++) {
        if (base + (float)sp[i] > budget) { atomicMin(&s_i1, i); break; }
    }
    __syncthreads();
    int i1 = min(s_i1, n);

    // parallel accept for i < i1 -> bitmap (idempotent OR)
    for (int i = t; i < i1; i += 1024) {
        int p = b * HWPX + (int)((sk[i] >> 8) & 0xFFFFu);
        atomicOr(&g_winbits[p >> 5], 1u << (p & 31));
    }

    // tiny serial tail from i1 (capacity < 4; breaks after <=3 cost-1 accepts)
    if (t == 0 && i1 < n) {
        float usage = base + (float)(i1 > 0 ? (int)sp[i1-1] : 0);
        for (int i = i1; i < n; i++) {
            if (usage + 1.0f > budget) break;
            unsigned long long k = sk[i];
            float c = (float)cost_of((int)(k & 0xFFu));
            if (usage + c <= budget) {
                usage += c;
                int p = b * HWPX + (int)((k >> 8) & 0xFFFFu);
                atomicOr(&g_winbits[p >> 5], 1u << (p & 31));
            }
        }
    }
}

// ---- big masked copy: computes accept in-place (no selmap) + writes out_sel ----
__global__ void kMaskedCopy(const float* __restrict__ collab, float* __restrict__ out,
                            float* __restrict__ out_sel) {
    int tid = blockIdx.x * blockDim.x + threadIdx.x;
    int row = tid >> 14;               // b*256 + c
    int o   = (tid & 16383) << 2;      // hw offset, multiple of 4
    int c   = row & 255;
    int b   = row >> 8;
    int grp = (c < 64) ? 0 : (c < 192) ? 1 : 2;
    size_t idx = ((size_t)row << 16) + (size_t)o;
    int p0 = b * HWPX + o;

    pdl_wait();   // kSelect done (g_b0/g_winbits final; g_hist no longer read)
    if (tid < (int)(sizeof(g_hist)/sizeof(uint4)))      // 327680 threads zero g_hist
        ((uint4*)g_hist)[tid] = make_uint4(0u, 0u, 0u, 0u);

    uint4  d4 = *(const uint4*)(g_dsc + p0);           // L2-resident planes
    uchar4 g4 = *(const uchar4*)(g_g8 + p0);
    unsigned wb = g_winbits[p0 >> 5] >> (o & 31);
    int b0 = g_b0[b];

    unsigned dsc[4] = {d4.x, d4.y, d4.z, d4.w};
    int gv[4] = {g4.x, g4.y, g4.z, g4.w};
    bool acc[4], m[4];
    #pragma unroll
    for (int k = 0; k < 4; k++) {
        acc[k] = (dsc[k] < 0x80000000u && (int)(dsc[k] >> BSHIFT) < b0)
               || ((wb >> k) & 1u);
        m[k] = acc[k] && (gv[k] == grp);
    }

    if (c == 0) {   // one channel-row per batch also materializes out_sel
        float4 sv;
        sv.x = acc[0] ? (float)gv[0] : -1.0f;
        sv.y = acc[1] ? (float)gv[1] : -1.0f;
        sv.z = acc[2] ? (float)gv[2] : -1.0f;
        sv.w = acc[3] ? (float)gv[3] : -1.0f;
        *(float4*)(out_sel + p0) = sv;
    }

    float4 v = make_float4(0.f, 0.f, 0.f, 0.f);
    if (m[0] | m[1] | m[2] | m[3]) {
        float4 w = *(const float4*)(collab + idx);
        if (m[0]) v.x = w.x;
        if (m[1]) v.y = w.y;
        if (m[2]) v.z = w.z;
        if (m[3]) v.w = w.w;
    }
    *(float4*)(out + idx) = v;
}

static void launch_pdl(void* func, dim3 grid, dim3 block, void** args) {
    cudaLaunchConfig_t cfg = {};
    cfg.gridDim = grid; cfg.blockDim = block;
    cudaLaunchAttribute attr[1];
    attr[0].id = cudaLaunchAttributeProgrammaticStreamSerialization;
    attr[0].val.programmaticStreamSerializationAllowed = 1;
    cfg.attrs = attr; cfg.numAttrs = 1;
    cudaLaunchKernelExC(&cfg, func, args);
}

extern "C" void kernel_launch(void* const* d_in, const int* in_sizes, int n_in,
                              void* d_out, int out_size) {
    const float* collab = (const float*)d_in[0];
    const float* util   = (const float*)d_in[1];
    const void*  budget = d_in[2];
    float* out     = (float*)d_out;
    float* out_sel = out + (size_t)NP * NCH;

    kArgmax<<<NP/2/256, 256>>>(util);

    { void* args[] = { (void*)&budget };
      launch_pdl((void*)kSelect, dim3(NB), dim3(1024), args); }
    { void* args[] = { (void*)&collab, (void*)&out, (void*)&out_sel };
      launch_pdl((void*)kMaskedCopy, dim3((NP/4)*NCH/256), dim3(256), args); }
}

// round 14
// speedup vs baseline: 1.0514x; 1.0514x over previous
#include <cuda_runtime.h>
#include <cstdint>

#define NB      5
#define HWPX    65536
#define NP      (NB*HWPX)
#define NCH     256
#define BSHIFT  14                    // bucket = dsc >> 14 (18-bit buckets)
#define NBUCK   131072                // valid dsc < 0x80000000 -> bucket < 131072
#define TILESZ  4096
#define NTILE   (NBUCK/TILESZ)        // 32
#define WCAP    4096

// PDL: park until predecessor kernel completes (no-op if not launched dependent)
__device__ __forceinline__ void pdl_wait() {
    asm volatile("griddepcontrol.wait;" ::: "memory");
}

// ---- static device scratch (allocation-free; zero-initialized at load) ----
__device__ unsigned int       g_dsc[NP];           // descending-order key of best utility
__device__ unsigned char      g_g8[NP];            // argmax group 0/1/2
__device__ signed char        g_selmap[NP];        // accepted group or -1
__device__ unsigned long long g_hist[NB*NBUCK];    // packed: cost | c1<<20 | c2<<40
__device__ unsigned int       g_winbits[NP/32];    // accepted-window bitmap (idempotent OR)
__device__ int                g_b0[NB];

__device__ __forceinline__ float load_budget(const void* ptr) {
    int iv = *(const int*)ptr;                       // int32 or float32 scalar
    if (iv > 0 && iv < 100000000) return (float)iv;
    return __int_as_float(iv);
}
__device__ __forceinline__ int cost_of(int g) { return (g == 0) ? 4 : (g == 1) ? 2 : 1; }

__device__ __forceinline__ void do_pixel(int p, float u0, float u1, float u2,
                                         unsigned* dsc_o, unsigned char* g_o) {
    int g = 0; float bu = u0;
    if (u1 > bu) { bu = u1; g = 1; }   // strict >: first max wins (jnp.argmax)
    if (u2 > bu) { bu = u2; g = 2; }
    bool valid = bu > 0.0f;
    unsigned int x = __float_as_uint(bu);
    unsigned int dsc = ~((x & 0x80000000u) ? ~x : (x | 0x80000000u)); // descending map
    if (!valid) dsc = 0xFFFFFFFFu;
    *dsc_o = dsc; *g_o = (unsigned char)g;
    if (valid) {
        unsigned long long inc = (unsigned long long)cost_of(g)
            | ((unsigned long long)(g == 1) << 20)
            | ((unsigned long long)(g == 2) << 40);
        atomicAdd(&g_hist[(size_t)(p >> 16) * NBUCK + (dsc >> BSHIFT)], inc);
    }
}

// ---- per-pixel argmax + packed histogram, 4 px / thread, float4 loads ----
__global__ void kArgmax(const float* __restrict__ util) {
    int q  = blockIdx.x * blockDim.x + threadIdx.x;   // NP/4 threads
    int p0 = q << 2;
    const float4* u = (const float4*)(util + 3 * (size_t)p0);   // 12 floats = 3x float4
    float4 a = u[0], b = u[1], c = u[2];
    unsigned d4[4]; unsigned char gg[4];
    do_pixel(p0 + 0, a.x, a.y, a.z, &d4[0], &gg[0]);
    do_pixel(p0 + 1, a.w, b.x, b.y, &d4[1], &gg[1]);
    do_pixel(p0 + 2, b.z, b.w, c.x, &d4[2], &gg[2]);
    do_pixel(p0 + 3, c.y, c.z, c.w, &d4[3], &gg[3]);
    *(uint4*)(g_dsc + p0) = make_uint4(d4[0], d4[1], d4[2], d4[3]);
    *(uchar4*)(g_g8 + p0) = make_uchar4(gg[0], gg[1], gg[2], gg[3]);
}

// ---- fused selection: 1 block (1024 thr) per batch ----
__global__ void kSelect(const void* __restrict__ budget_p) {
    __shared__ unsigned s_tile[NTILE];
    __shared__ unsigned s_wsum[32];
    __shared__ int s_ctile, s_b0, s_b1, s_n, s_i1;
    __shared__ unsigned s_cumbase, s_Sb;
    __shared__ unsigned long long sk[WCAP];     // 32KB window keys
    __shared__ unsigned short sp[WCAP];         // 8KB inclusive cost prefix (<=16384)
    __shared__ int s_tsum[32];

    int b = blockIdx.x, t = threadIdx.x;
    int wid = t >> 5, lane = t & 31;
    float budget = load_budget(budget_p) / (float)NB;
    const unsigned long long* hist = g_hist + (size_t)b * NBUCK;

    if (t == 0) { s_ctile = -1; s_cumbase = 0; s_b0 = NBUCK; s_Sb = 0;
                  s_n = 0; s_i1 = 0x7FFFFFFF; }
    pdl_wait();   // kArgmax results (g_hist/g_dsc/g_g8) must be complete

    // warp w sums tile w (4096 buckets), coalesced
    unsigned sum = 0;
    #pragma unroll 8
    for (int j = 0; j < TILESZ/32; j++)
        sum += (unsigned)(hist[wid*TILESZ + j*32 + lane] & 0xFFFFFu);
    #pragma unroll
    for (int off = 16; off > 0; off >>= 1) sum += __shfl_down_sync(0xffffffffu, sum, off);
    if (lane == 0) s_tile[wid] = sum;
    __syncthreads();

    if (t == 0) {   // tile-level crossing
        unsigned cum = 0;
        for (int q = 0; q < NTILE; q++) {
            unsigned c = s_tile[q];
            if ((float)(cum + c) > budget) { s_ctile = q; s_cumbase = cum; break; }
            cum += c;
        }
    }
    __syncthreads();
    int ctile = s_ctile;

    if (ctile >= 0) {   // in-tile scan: 4 buckets per thread over 4096 buckets
        int base = ctile*TILESZ + t*4;
        unsigned c4[4]; unsigned s = 0;
        #pragma unroll
        for (int k = 0; k < 4; k++) { c4[k] = (unsigned)(hist[base+k] & 0xFFFFFu); s += c4[k]; }
        unsigned inc = s;
        #pragma unroll
        for (int off = 1; off < 32; off <<= 1) {
            unsigned v = __shfl_up_sync(0xffffffffu, inc, off);
            if (lane >= off) inc += v;
        }
        if (lane == 31) s_wsum[wid] = inc;
        __syncthreads();
        if (wid == 0) {
            unsigned w = s_wsum[lane];
            #pragma unroll
            for (int off = 1; off < 32; off <<= 1) {
                unsigned v = __shfl_up_sync(0xffffffffu, w, off);
                if (lane >= off) w += v;
            }
            s_wsum[lane] = w;
        }
        __syncthreads();
        unsigned cum = s_cumbase + (inc - s) + ((wid > 0) ? s_wsum[wid-1] : 0u);
        #pragma unroll
        for (int k = 0; k < 4; k++) {   // unique first crossing among this thread's 4
            unsigned nxt = cum + c4[k];
            if ((float)nxt > budget && (float)cum <= budget) { s_b0 = base + k; s_Sb = cum; }
            cum = nxt;
        }
        __syncthreads();
    }

    int b0 = s_b0;
    if (t == 0) g_b0[b] = b0;
    if (b0 >= NBUCK) return;   // no crossing: phase-1 accepts everything valid

    if (wid == 0) {   // extend window bucket-by-bucket until >=8 cost-1 items beyond b0
        int c2cum = 0, pos = b0 + 1, b1 = NBUCK-1; bool done = false;
        while (!done && pos < NBUCK) {
            int idx = pos + lane;
            unsigned long long h = (idx < NBUCK) ? hist[idx] : 0ull;
            int k = (int)((h >> 40) & 0xFFFFFull);
            int inck = k;
            #pragma unroll
            for (int off = 1; off < 32; off <<= 1) {
                int v = __shfl_up_sync(0xffffffffu, inck, off);
                if (lane >= off) inck += v;
            }
            int tot = __shfl_sync(0xffffffffu, inck, 31);
            unsigned m = __ballot_sync(0xffffffffu, c2cum + inck >= 8);
            if (m) { b1 = min(pos + (__ffs(m) - 1), NBUCK-1); done = true; }
            else   { c2cum += tot; pos += 32; }
        }
        if (lane == 0) s_b1 = b1;
    }
    __syncthreads();
    unsigned b0u = (unsigned)b0, b1u = (unsigned)s_b1;

    // gather window items by scanning this batch's dsc plane (256KB, coalesced)
    const uint4* dscv = (const uint4*)(g_dsc + (size_t)b * HWPX);
    for (int i = t; i < HWPX/4; i += 1024) {
        uint4 d = dscv[i];
        unsigned da[4] = {d.x, d.y, d.z, d.w};
        #pragma unroll
        for (int k = 0; k < 4; k++) {
            unsigned bucket = da[k] >> BSHIFT;   // invalid dsc -> bucket 0x3FFFF > b1
            if (bucket >= b0u && bucket <= b1u) {
                int pix = i*4 + k;
                int g = (int)g_g8[b*HWPX + pix];
                int idx = atomicAdd(&s_n, 1);
                if (idx < WCAP)
                    sk[idx] = ((unsigned long long)da[k] << 24)
                            | ((unsigned long long)pix << 8) | (unsigned long long)g;
            }
        }
    }
    __syncthreads();
    int n = min(s_n, WCAP);

    // exact ranking sort (unique keys -> permutation)
    unsigned long long myk[4]; int myr[4]; int cnt = 0;
    for (int i = t; i < n; i += 1024) {
        unsigned long long k = sk[i];
        int r = 0;
        for (int j = 0; j < n; j++) r += (sk[j] < k);
        myk[cnt] = k; myr[cnt] = r; cnt++;
    }
    __syncthreads();
    for (int q = 0; q < cnt; q++) sk[myr[q]] = myk[q];
    __syncthreads();

    // block-wide inclusive prefix sum of costs (4 items / thread)
    int lo = t * 4, hi = min(lo + 4, n);
    int run = 0;
    for (int i = lo; i < hi; i++) { run += cost_of((int)(sk[i] & 0xFFu)); sp[i] = (unsigned short)run; }
    int tot = run, inc2 = tot;
    #pragma unroll
    for (int off = 1; off < 32; off <<= 1) {
        int v = __shfl_up_sync(0xffffffffu, inc2, off);
        if (lane >= off) inc2 += v;
    }
    if (lane == 31) s_tsum[wid] = inc2;
    __syncthreads();
    if (wid == 0) {
        int w = s_tsum[lane];
        #pragma unroll
        for (int off = 1; off < 32; off <<= 1) {
            int v = __shfl_up_sync(0xffffffffu, w, off);
            if (lane >= off) w += v;
        }
        s_tsum[lane] = w;
    }
    __syncthreads();
    int chunk_off = (inc2 - tot) + ((wid > 0) ? s_tsum[wid-1] : 0);
    for (int i = lo; i < hi; i++) sp[i] = (unsigned short)(sp[i] + chunk_off);
    __syncthreads();

    float base = (float)s_Sb;
    // first rejection index: first i with base + sp[i] > budget
    for (int i = lo; i < hi; i++) {
        if (base + (float)sp[i] > budget) { atomicMin(&s_i1, i); break; }
    }
    __syncthreads();
    int i1 = min(s_i1, n);

    // parallel accept for i < i1 -> bitmap (idempotent OR)
    for (int i = t; i < i1; i += 1024) {
        int p = b * HWPX + (int)((sk[i] >> 8) & 0xFFFFu);
        atomicOr(&g_winbits[p >> 5], 1u << (p & 31));
    }

    // tiny serial tail from i1 (capacity < 4; breaks after <=3 cost-1 accepts)
    if (t == 0 && i1 < n) {
        float usage = base + (float)(i1 > 0 ? (int)sp[i1-1] : 0);
        for (int i = i1; i < n; i++) {
            if (usage + 1.0f > budget) break;
            unsigned long long k = sk[i];
            float c = (float)cost_of((int)(k & 0xFFu));
            if (usage + c <= budget) {
                usage += c;
                int p = b * HWPX + (int)((k >> 8) & 0xFFFFu);
                atomicOr(&g_winbits[p >> 5], 1u << (p & 31));
            }
        }
    }
}

// ---- final per-pixel decision (2 px / thread, no atomics) ----
__global__ void kGather(float* __restrict__ out_sel) {
    int q = blockIdx.x * blockDim.x + threadIdx.x;   // NP/2 threads
    int p0 = q << 1;
    int b = p0 >> 16;
    pdl_wait();   // kSelect results (g_b0/g_winbits) must be complete
    uint2 d2 = *(const uint2*)(g_dsc + p0);
    uchar2 gg = *(const uchar2*)(g_g8 + p0);
    int b0 = g_b0[b];
    unsigned wb = g_winbits[p0 >> 5];
    unsigned dsc[2] = {d2.x, d2.y};
    int gv[2] = {gg.x, gg.y};
    signed char sm[2]; float so[2];
    #pragma unroll
    for (int k = 0; k < 2; k++) {
        bool acc = (dsc[k] < 0x80000000u && (int)(dsc[k] >> BSHIFT) < b0)
                 || ((wb >> ((p0 & 31) + k)) & 1u);
        sm[k] = acc ? (signed char)gv[k] : (signed char)-1;
        so[k] = acc ? (float)gv[k] : -1.0f;
    }
    *(char2*)(g_selmap + p0) = make_char2(sm[0], sm[1]);
    *(float2*)(out_sel + p0) = make_float2(so[0], so[1]);
}

// ---- big HBM-bound masked copy (frozen R3 winner) + hist re-zero for next replay ----
__global__ void kMaskedCopy(const float* __restrict__ collab, float* __restrict__ out) {
    int tid = blockIdx.x * blockDim.x + threadIdx.x;
    int row = tid >> 14;               // b*256 + c
    int o   = (tid & 16383) << 2;      // hw offset, multiple of 4
    int c   = row & 255;
    int b   = row >> 8;
    int grp = (c < 64) ? 0 : (c < 192) ? 1 : 2;
    size_t idx = ((size_t)row << 16) + (size_t)o;
    pdl_wait();   // selmap (kGather) complete; kSelect done reading g_hist
    if (tid < (int)(sizeof(g_hist)/sizeof(uint4)))      // 327680 threads zero g_hist
        ((uint4*)g_hist)[tid] = make_uint4(0u, 0u, 0u, 0u);
    char4 s4 = *(const char4*)(g_selmap + b * HWPX + o);
    bool m0 = (s4.x == grp), m1 = (s4.y == grp), m2 = (s4.z == grp), m3 = (s4.w == grp);
    float4 v = make_float4(0.f, 0.f, 0.f, 0.f);
    if (m0 | m1 | m2 | m3) {
        v = *(const float4*)(collab + idx);
        if (!m0) v.x = 0.f;
        if (!m1) v.y = 0.f;
        if (!m2) v.z = 0.f;
        if (!m3) v.w = 0.f;
    }
    *(float4*)(out + idx) = v;
}

static void launch_pdl(void* func, dim3 grid, dim3 block, void** args) {
    cudaLaunchConfig_t cfg = {};
    cfg.gridDim = grid; cfg.blockDim = block;
    cudaLaunchAttribute attr[1];
    attr[0].id = cudaLaunchAttributeProgrammaticStreamSerialization;
    attr[0].val.programmaticStreamSerializationAllowed = 1;
    cfg.attrs = attr; cfg.numAttrs = 1;
    cudaLaunchKernelExC(&cfg, func, args);
}

extern "C" void kernel_launch(void* const* d_in, const int* in_sizes, int n_in,
                              void* d_out, int out_size) {
    const float* collab = (const float*)d_in[0];
    const float* util   = (const float*)d_in[1];
    const void*  budget = d_in[2];
    float* out     = (float*)d_out;
    float* out_sel = out + (size_t)NP * NCH;

    kArgmax<<<NP/4/256, 256>>>(util);

    { void* args[] = { (void*)&budget };
      launch_pdl((void*)kSelect, dim3(NB), dim3(1024), args); }
    { void* args[] = { (void*)&out_sel };
      launch_pdl((void*)kGather, dim3(NP/2/256), dim3(256), args); }
    { void* args[] = { (void*)&collab, (void*)&out };
      launch_pdl((void*)kMaskedCopy, dim3((NP/4)*NCH/256), dim3(256), args); }
}